// round 5
// baseline (speedup 1.0000x reference)
#include <cuda_runtime.h>

#define IMG 4096
#define TILE 56            // owned pixels per tile (both dims)
#define NROWS 66           // smem rows (input halo 5)
#define SSTR 72            // smem row stride in floats
#define NITER 5
#define NTILES ((IMG + TILE - 1) / TILE)     // 74
#define NBLK (NTILES * NTILES)               // 5476

// [0] = gt_sum, [1] = weighted fn sum  (reset by the last block each run)
__device__ float g_sums[2];
__device__ unsigned int g_count;

typedef unsigned long long u64;

__device__ __forceinline__ u64 pk2(float lo, float hi) {
    u64 r; asm("mov.b64 %0, {%1, %2};" : "=l"(r) : "f"(lo), "f"(hi)); return r;
}
__device__ __forceinline__ float2 upk2(u64 v) {
    float2 f; asm("mov.b64 {%0, %1}, %2;" : "=f"(f.x), "=f"(f.y) : "l"(v)); return f;
}
__device__ __forceinline__ u64 add2(u64 a, u64 b) {
    u64 r; asm("add.rn.f32x2 %0, %1, %2;" : "=l"(r) : "l"(a), "l"(b)); return r;
}
__device__ __forceinline__ u64 mul2(u64 a, u64 b) {
    u64 r; asm("mul.rn.f32x2 %0, %1, %2;" : "=l"(r) : "l"(a), "l"(b)); return r;
}
__device__ __forceinline__ u64 fma2(u64 a, u64 b, u64 c) {
    u64 r; asm("fma.rn.f32x2 %0, %1, %2, %3;" : "=l"(r) : "l"(a), "l"(b), "l"(c)); return r;
}
__device__ __forceinline__ float tanh_fast(float x) {
    float r; asm("tanh.approx.f32 %0, %1;" : "=f"(r) : "f"(x)); return r;
}
__device__ __forceinline__ float clamp01(float x) {
    return fminf(fmaxf(x, 0.0f), 1.0f);
}

__global__ void __launch_bounds__(256)
fused_kernel(const float* __restrict__ pred, const float* __restrict__ gt,
             float* __restrict__ out) {
    __shared__ float sA[NROWS * SSTR];
    __shared__ float sB[NROWS * SSTR];
    __shared__ float red_w[8], red_g[8];

    const int tx  = threadIdx.x;           // 0..15
    const int ty  = threadIdx.y;           // 0..15
    const int tid = ty * 16 + tx;

    const int ox  = blockIdx.x * TILE - 4;  // global col of logical col 0
    const int gy0 = blockIdx.y * TILE - 5;  // global row of smem row 0

    // ---- fill sA with pred over rows 0..65, logical cols -1..64 (zero-pad OOB)
    for (int e = tid; e < NROWS * NROWS; e += 256) {
        const int r = e / NROWS;
        const int c = e - r * NROWS;
        const int gy = gy0 + r;
        const int gx = ox - 1 + c;
        float v = 0.0f;
        if ((unsigned)gy < (unsigned)IMG && (unsigned)gx < (unsigned)IMG)
            v = pred[(size_t)gy * IMG + gx];
        sA[r * SSTR + c + 3] = v;
    }

    // ---- gt for this thread's 4x4 patch (packed pairs)
    const bool owner = (tx >= 1) && (tx < 15) && (ty >= 1) && (ty < 15);
    const int gx0 = ox + 4 * tx;
    u64 g01[4], g23[4];
    float gt_local = 0.0f;
    #pragma unroll
    for (int i = 0; i < 4; ++i) {
        const int gy = gy0 + 1 + 4 * ty + i;
        float4 g = make_float4(0.f, 0.f, 0.f, 0.f);
        if ((unsigned)gy < (unsigned)IMG) {
            if (gx0 >= 0 && gx0 + 3 < IMG) {
                g = *(const float4*)(gt + (size_t)gy * IMG + gx0);
            } else {
                const float* row = gt + (size_t)gy * IMG;
                if ((unsigned)(gx0 + 0) < (unsigned)IMG) g.x = row[gx0 + 0];
                if ((unsigned)(gx0 + 1) < (unsigned)IMG) g.y = row[gx0 + 1];
                if ((unsigned)(gx0 + 2) < (unsigned)IMG) g.z = row[gx0 + 2];
                if ((unsigned)(gx0 + 3) < (unsigned)IMG) g.w = row[gx0 + 3];
            }
        }
        g01[i] = pk2(g.x, g.y);
        g23[i] = pk2(g.z, g.w);
        gt_local += (g.x + g.y) + (g.z + g.w);
    }
    if (!owner) gt_local = 0.0f;

    __syncthreads();

    float* cur = sA;
    float* nxt = sB;
    const float wts[NITER] = {1.0f, 4.0f, 9.0f, 16.0f, 25.0f};
    float wacc = 0.0f;

    const u64 C10  = pk2(10.0f, 10.0f);
    const u64 CM10 = pk2(-10.0f, -10.0f);
    const u64 CM5  = pk2(-5.0f, -5.0f);
    const u64 CH   = pk2(0.5f, 0.5f);

    const int base = (4 * ty) * SSTR + 4 + 4 * tx;
    const bool is_l = (tx == 0);
    const bool is_r = (tx == 15);

    #pragma unroll
    for (int k = 1; k <= NITER; ++k) {
        // 6 rows: center float4 via LDS.128; edge neighbors via warp shuffle
        u64 pA[6], pB[6], h01[6], h23[6];
        #pragma unroll
        for (int r = 0; r < 6; ++r) {
            const float* p = cur + base + r * SSTR;
            const float4 c = *(const float4*)p;
            float lw = __shfl_up_sync(0xffffffffu, c.w, 1);
            float rx = __shfl_down_sync(0xffffffffu, c.x, 1);
            const float l  = is_l ? p[-1] : lw;
            const float rr = is_r ? p[4]  : rx;
            pA[r] = pk2(c.x, c.y);
            pB[r] = pk2(c.z, c.w);
            const u64 pL = pk2(l,   c.x);
            const u64 pM = pk2(c.y, c.z);
            const u64 pR = pk2(c.w, rr);
            h01[r] = add2(add2(pL, pA[r]), pM);
            h23[r] = add2(add2(pM, pB[r]), pR);
        }

        u64 facc = 0;   // (0.0f, 0.0f)
        #pragma unroll
        for (int i = 0; i < 4; ++i) {
            const u64 b01 = add2(add2(h01[i], h01[i + 1]), h01[i + 2]);
            const u64 b23 = add2(add2(h23[i], h23[i + 1]), h23[i + 2]);
            const float2 bA = upk2(b01);
            const float2 bB = upk2(b23);
            const u64 d01 = pk2(clamp01(bA.x), clamp01(bA.y));
            const u64 d23 = pk2(clamp01(bB.x), clamp01(bB.y));

            // z = 10*d - 10*p - 5
            const u64 z01 = fma2(d01, C10, fma2(pA[i + 1], CM10, CM5));
            const u64 z23 = fma2(d23, C10, fma2(pB[i + 1], CM10, CM5));
            const float2 zA = upk2(z01);
            const float2 zB = upk2(z23);
            const u64 t01 = pk2(tanh_fast(zA.x), tanh_fast(zA.y));
            const u64 t23 = pk2(tanh_fast(zB.x), tanh_fast(zB.y));

            // sharp = 0.5*t + 0.5 ; fn = g*sharp ; pn = p + fn
            const u64 fn01 = mul2(fma2(t01, CH, CH), g01[i]);
            const u64 fn23 = mul2(fma2(t23, CH, CH), g23[i]);
            facc = add2(facc, fn01);
            facc = add2(facc, fn23);

            if (k < NITER) {
                const u64 pn01 = add2(pA[i + 1], fn01);
                const u64 pn23 = add2(pB[i + 1], fn23);
                const int pr = 1 + 4 * ty + i;               // output smem row
                const bool row_ok = (pr >= k) && (pr <= 65 - k);
                if (row_ok) {
                    const float2 q0 = upk2(pn01);
                    const float2 q1 = upk2(pn23);
                    const int pc0 = 4 * tx;                  // logical col
                    const bool col_full = (pc0 >= k - 1) && (pc0 + 3 <= 64 - k);
                    float* dst = nxt + pr * SSTR + 4 + pc0;
                    if (col_full) {
                        float4 pn4 = make_float4(q0.x, q0.y, q1.x, q1.y);
                        *(float4*)dst = pn4;
                    } else {
                        if (pc0 + 0 >= k - 1 && pc0 + 0 <= 64 - k) dst[0] = q0.x;
                        if (pc0 + 1 >= k - 1 && pc0 + 1 <= 64 - k) dst[1] = q0.y;
                        if (pc0 + 2 >= k - 1 && pc0 + 2 <= 64 - k) dst[2] = q1.x;
                        if (pc0 + 3 >= k - 1 && pc0 + 3 <= 64 - k) dst[3] = q1.y;
                    }
                }
            }
        }
        if (owner) {
            const float2 f = upk2(facc);
            wacc += wts[k - 1] * (f.x + f.y);
        }

        if (k < NITER) {
            __syncthreads();
            float* t = cur; cur = nxt; nxt = t;
        }
    }

    // ---- block reduction, one atomic each per block
    #pragma unroll
    for (int o = 16; o > 0; o >>= 1) {
        wacc     += __shfl_down_sync(0xffffffffu, wacc, o);
        gt_local += __shfl_down_sync(0xffffffffu, gt_local, o);
    }
    const int lane = tid & 31;
    const int wid  = tid >> 5;
    if (lane == 0) { red_w[wid] = wacc; red_g[wid] = gt_local; }
    __syncthreads();
    if (tid == 0) {
        float v = 0.0f, g = 0.0f;
        #pragma unroll
        for (int i = 0; i < 8; ++i) { v += red_w[i]; g += red_g[i]; }
        atomicAdd(&g_sums[1], v);
        atomicAdd(&g_sums[0], g);
        __threadfence();
        const unsigned int done = atomicAdd(&g_count, 1u);
        if (done == NBLK - 1) {
            // last block: all other blocks' atomics are visible (L2-coherent)
            const float s1 = atomicAdd(&g_sums[1], 0.0f);
            const float s0 = atomicAdd(&g_sums[0], 0.0f);
            out[0] = s1 / s0;
            // reset for next graph replay
            g_sums[0] = 0.0f;
            g_sums[1] = 0.0f;
            g_count   = 0u;
        }
    }
}

extern "C" void kernel_launch(void* const* d_in, const int* in_sizes, int n_in,
                              void* d_out, int out_size) {
    (void)in_sizes; (void)n_in; (void)out_size;
    const float* pred = (const float*)d_in[0];
    const float* gt   = (const float*)d_in[1];
    float* out        = (float*)d_out;

    dim3 block(16, 16);
    dim3 grid(NTILES, NTILES);
    fused_kernel<<<grid, block>>>(pred, gt, out);
}

// round 6
// speedup vs baseline: 1.3217x; 1.3217x over previous
#include <cuda_runtime.h>

#define IMG 4096
#define TILE 56            // owned pixels per tile (both dims)
#define NROWS 66           // smem rows (input halo 5)
#define SSTR 72            // smem row stride in floats (= 18 float4)
#define NITER 5
#define NTILES ((IMG + TILE - 1) / TILE)     // 74
#define NBLK (NTILES * NTILES)               // 5476

// [0] = gt_sum, [1] = weighted fn sum  (reset by the last block each run)
__device__ float g_sums[2];
__device__ unsigned int g_count;

__device__ __forceinline__ float tanh_fast(float x) {
    float r; asm("tanh.approx.f32 %0, %1;" : "=f"(r) : "f"(x)); return r;
}
__device__ __forceinline__ float clamp01(float x) {
    return fminf(fmaxf(x, 0.0f), 1.0f);
}

__global__ void __launch_bounds__(256)
fused_kernel(const float* __restrict__ pred, const float* __restrict__ gt,
             float* __restrict__ out) {
    __shared__ float sA[NROWS * SSTR];
    __shared__ float sB[NROWS * SSTR];
    __shared__ float red_w[8], red_g[8];

    const int tx  = threadIdx.x;            // 0..15
    const int ty  = threadIdx.y;            // 0..15
    const int tid = ty * 16 + tx;

    // smem col s <-> global col gx0b + s ; smem row r <-> global row gy0 + r
    const int gx0b = blockIdx.x * TILE - 8;  // 16B-aligned window start
    const int gy0  = blockIdx.y * TILE - 5;

    // ---- vectorized fill: 66 rows x 18 float4 (zero-pad OOB; vector-granular
    //      OOB is exact because IMG and the window start are 4-aligned)
    #pragma unroll
    for (int e = tid; e < NROWS * 18; e += 256) {
        const int r  = e / 18;
        const int ci = e - r * 18;
        const int gy = gy0 + r;
        const int gx = gx0b + 4 * ci;
        float4 v = make_float4(0.f, 0.f, 0.f, 0.f);
        if ((unsigned)gy < (unsigned)IMG && (unsigned)gx <= (unsigned)(IMG - 4))
            v = *(const float4*)(pred + (size_t)gy * IMG + gx);
        *(float4*)&sA[r * SSTR + 4 * ci] = v;
    }

    // ---- gt for this thread's 4x4 patch; keep gh = 0.5*g
    const bool owner = (tx >= 1) && (tx < 15) && (ty >= 1) && (ty < 15);
    const int gxp = gx0b + 4 + 4 * tx;       // global col of thread's first px
    float gh[4][4];
    float gt_local = 0.0f;
    #pragma unroll
    for (int i = 0; i < 4; ++i) {
        const int gy = gy0 + 1 + 4 * ty + i;
        float4 g = make_float4(0.f, 0.f, 0.f, 0.f);
        if ((unsigned)gy < (unsigned)IMG) {
            if (gxp >= 0 && gxp + 3 < IMG) {
                g = *(const float4*)(gt + (size_t)gy * IMG + gxp);
            } else {
                const float* row = gt + (size_t)gy * IMG;
                if ((unsigned)(gxp + 0) < (unsigned)IMG) g.x = row[gxp + 0];
                if ((unsigned)(gxp + 1) < (unsigned)IMG) g.y = row[gxp + 1];
                if ((unsigned)(gxp + 2) < (unsigned)IMG) g.z = row[gxp + 2];
                if ((unsigned)(gxp + 3) < (unsigned)IMG) g.w = row[gxp + 3];
            }
        }
        gt_local += (g.x + g.y) + (g.z + g.w);
        gh[i][0] = 0.5f * g.x; gh[i][1] = 0.5f * g.y;
        gh[i][2] = 0.5f * g.z; gh[i][3] = 0.5f * g.w;
    }
    if (!owner) gt_local = 0.0f;

    __syncthreads();

    float* cur = sA;
    float* nxt = sB;
    const float wts[NITER] = {1.0f, 4.0f, 9.0f, 16.0f, 25.0f};
    float wacc = 0.0f;

    const int base = (4 * ty) * SSTR + 4 + 4 * tx;
    const bool is_l = (tx == 0);
    const bool is_r = (tx == 15);

    #pragma unroll
    for (int k = 1; k <= NITER; ++k) {
        // 6 input rows; horizontal 3-taps via shared adjacent pairs (6 adds/row)
        float c[6][4];
        float h[6][4];
        #pragma unroll
        for (int r = 0; r < 6; ++r) {
            const float* p = cur + base + r * SSTR;
            const float4 cc = *(const float4*)p;
            const float lw = __shfl_up_sync(0xffffffffu, cc.w, 1);
            const float rx = __shfl_down_sync(0xffffffffu, cc.x, 1);
            const float l  = is_l ? p[-1] : lw;
            const float rr = is_r ? p[4]  : rx;
            const float pxy = cc.x + cc.y;
            const float pzw = cc.z + cc.w;
            h[r][0] = l    + pxy;
            h[r][1] = pxy  + cc.z;
            h[r][2] = cc.y + pzw;
            h[r][3] = pzw  + rr;
            c[r][0] = cc.x; c[r][1] = cc.y; c[r][2] = cc.z; c[r][3] = cc.w;
        }

        // vertical 3-taps via shared middle pairs (6 adds/col)
        float box[4][4];
        #pragma unroll
        for (int j = 0; j < 4; ++j) {
            const float p12 = h[1][j] + h[2][j];
            const float p34 = h[3][j] + h[4][j];
            box[0][j] = h[0][j] + p12;
            box[1][j] = p12 + h[3][j];
            box[2][j] = h[2][j] + p34;
            box[3][j] = p34 + h[5][j];
        }

        float fn_iter = 0.0f;
        #pragma unroll
        for (int i = 0; i < 4; ++i) {
            float fn[4];
            #pragma unroll
            for (int j = 0; j < 4; ++j) {
                const float p = c[i + 1][j];
                const float d = clamp01(box[i][j]);
                // z = 10*d - 10*p - 5 ; sharp = 0.5*tanh(z)+0.5 ; fn = g*sharp
                const float z = fmaf(10.0f, d, fmaf(-10.0f, p, -5.0f));
                const float t = tanh_fast(z);
                fn[j] = fmaf(gh[i][j], t, gh[i][j]);
                fn_iter += fn[j];
            }

            if (k < NITER) {
                const int pr = 1 + 4 * ty + i;               // output smem row
                const bool row_ok = (pr >= k) && (pr <= 65 - k);
                if (row_ok) {
                    const int pc0 = 4 * tx;                  // logical col
                    const bool col_full = (pc0 >= k - 1) && (pc0 + 3 <= 64 - k);
                    float* dst = nxt + pr * SSTR + 4 + pc0;
                    const float pn0 = c[i + 1][0] + fn[0];
                    const float pn1 = c[i + 1][1] + fn[1];
                    const float pn2 = c[i + 1][2] + fn[2];
                    const float pn3 = c[i + 1][3] + fn[3];
                    if (col_full) {
                        *(float4*)dst = make_float4(pn0, pn1, pn2, pn3);
                    } else {
                        if (pc0 + 0 >= k - 1 && pc0 + 0 <= 64 - k) dst[0] = pn0;
                        if (pc0 + 1 >= k - 1 && pc0 + 1 <= 64 - k) dst[1] = pn1;
                        if (pc0 + 2 >= k - 1 && pc0 + 2 <= 64 - k) dst[2] = pn2;
                        if (pc0 + 3 >= k - 1 && pc0 + 3 <= 64 - k) dst[3] = pn3;
                    }
                }
            }
        }
        if (owner) wacc += wts[k - 1] * fn_iter;

        if (k < NITER) {
            __syncthreads();
            float* t = cur; cur = nxt; nxt = t;
        }
    }

    // ---- block reduction, one atomic each per block; last block finalizes
    #pragma unroll
    for (int o = 16; o > 0; o >>= 1) {
        wacc     += __shfl_down_sync(0xffffffffu, wacc, o);
        gt_local += __shfl_down_sync(0xffffffffu, gt_local, o);
    }
    const int lane = tid & 31;
    const int wid  = tid >> 5;
    if (lane == 0) { red_w[wid] = wacc; red_g[wid] = gt_local; }
    __syncthreads();
    if (tid == 0) {
        float v = 0.0f, g = 0.0f;
        #pragma unroll
        for (int i = 0; i < 8; ++i) { v += red_w[i]; g += red_g[i]; }
        atomicAdd(&g_sums[1], v);
        atomicAdd(&g_sums[0], g);
        __threadfence();
        const unsigned int done = atomicAdd(&g_count, 1u);
        if (done == NBLK - 1) {
            const float s1 = atomicAdd(&g_sums[1], 0.0f);
            const float s0 = atomicAdd(&g_sums[0], 0.0f);
            out[0] = s1 / s0;
            g_sums[0] = 0.0f;
            g_sums[1] = 0.0f;
            g_count   = 0u;
        }
    }
}

extern "C" void kernel_launch(void* const* d_in, const int* in_sizes, int n_in,
                              void* d_out, int out_size) {
    (void)in_sizes; (void)n_in; (void)out_size;
    const float* pred = (const float*)d_in[0];
    const float* gt   = (const float*)d_in[1];
    float* out        = (float*)d_out;

    dim3 block(16, 16);
    dim3 grid(NTILES, NTILES);
    fused_kernel<<<grid, block>>>(pred, gt, out);
}

// round 7
// speedup vs baseline: 1.6785x; 1.2700x over previous
#include <cuda_runtime.h>

#define IMG 4096
#define TILE 56            // owned pixels per tile (both dims)
#define NROWS 66           // smem rows (input halo 5)
#define SSTR 72            // smem row stride in floats (= 18 float4)
#define NITER 5
#define NTILES ((IMG + TILE - 1) / TILE)     // 74
#define NBLK (NTILES * NTILES)               // 5476

// [0] = gt_sum, [1] = weighted fn sum  (reset by the last block each run)
__device__ float g_sums[2];
__device__ unsigned int g_count;

__device__ __forceinline__ float tanh_fast(float x) {
    float r; asm("tanh.approx.f32 %0, %1;" : "=f"(r) : "f"(x)); return r;
}
__device__ __forceinline__ float clamp01(float x) {
    return fminf(fmaxf(x, 0.0f), 1.0f);
}
__device__ __forceinline__ float4 add4(float4 a, float4 b) {
    return make_float4(a.x + b.x, a.y + b.y, a.z + b.z, a.w + b.w);
}

__global__ void __launch_bounds__(256, 4)
fused_kernel(const float* __restrict__ pred, const float* __restrict__ gt,
             float* __restrict__ out) {
    __shared__ float sA[NROWS * SSTR];
    __shared__ float sB[NROWS * SSTR];
    __shared__ float red_w[8], red_g[8];

    const int tx  = threadIdx.x;            // 0..15
    const int ty  = threadIdx.y;            // 0..15
    const int tid = ty * 16 + tx;

    const int gx0b = blockIdx.x * TILE - 8;  // 16B-aligned window start
    const int gy0  = blockIdx.y * TILE - 5;

    // ---- vectorized fill: 66 rows x 18 float4 (zero-pad OOB)
    for (int e = tid; e < NROWS * 18; e += 256) {
        const int r  = e / 18;
        const int ci = e - r * 18;
        const int gy = gy0 + r;
        const int gx = gx0b + 4 * ci;
        float4 v = make_float4(0.f, 0.f, 0.f, 0.f);
        if ((unsigned)gy < (unsigned)IMG && (unsigned)gx <= (unsigned)(IMG - 4))
            v = *(const float4*)(pred + (size_t)gy * IMG + gx);
        *(float4*)&sA[r * SSTR + 4 * ci] = v;
    }

    // ---- gt for this thread's 4x4 patch; keep gh = 0.5*g
    const bool owner = (tx >= 1) && (tx < 15) && (ty >= 1) && (ty < 15);
    const int gxp = gx0b + 4 + 4 * tx;
    float4 gh[4];
    float gt_local = 0.0f;
    #pragma unroll
    for (int i = 0; i < 4; ++i) {
        const int gy = gy0 + 1 + 4 * ty + i;
        float4 g = make_float4(0.f, 0.f, 0.f, 0.f);
        if ((unsigned)gy < (unsigned)IMG) {
            if (gxp >= 0 && gxp + 3 < IMG) {
                g = *(const float4*)(gt + (size_t)gy * IMG + gxp);
            } else {
                const float* row = gt + (size_t)gy * IMG;
                if ((unsigned)(gxp + 0) < (unsigned)IMG) g.x = row[gxp + 0];
                if ((unsigned)(gxp + 1) < (unsigned)IMG) g.y = row[gxp + 1];
                if ((unsigned)(gxp + 2) < (unsigned)IMG) g.z = row[gxp + 2];
                if ((unsigned)(gxp + 3) < (unsigned)IMG) g.w = row[gxp + 3];
            }
        }
        gt_local += (g.x + g.y) + (g.z + g.w);
        gh[i] = make_float4(0.5f * g.x, 0.5f * g.y, 0.5f * g.z, 0.5f * g.w);
    }
    if (!owner) gt_local = 0.0f;

    __syncthreads();

    float* cur = sA;
    float* nxt = sB;
    const float wts[NITER] = {1.0f, 4.0f, 9.0f, 16.0f, 25.0f};
    float wacc = 0.0f;

    const int base = (4 * ty) * SSTR + 4 + 4 * tx;
    const bool is_l = (tx == 0);
    const bool is_r = (tx == 15);
    const int pc0 = 4 * tx;

// Load smem row r (relative to base); produce horizontal 3-tap sums H (float4)
// and the raw center values C (float4).
#define LOAD_ROW(r, H, C) do {                                          \
        const float* _p = cur + base + (r) * SSTR;                      \
        const float4 _c = *(const float4*)_p;                           \
        const float _lw = __shfl_up_sync(0xffffffffu, _c.w, 1);         \
        const float _rx = __shfl_down_sync(0xffffffffu, _c.x, 1);       \
        const float _l  = is_l ? _p[-1] : _lw;                          \
        const float _rr = is_r ? _p[4]  : _rx;                          \
        const float _pxy = _c.x + _c.y;                                 \
        const float _pzw = _c.z + _c.w;                                 \
        (H).x = _l   + _pxy;  (H).y = _pxy + _c.z;                      \
        (H).z = _c.y + _pzw;  (H).w = _pzw + _rr;                       \
        (C) = _c;                                                       \
    } while (0)

// Emit output row i from BOX (vertical+horizontal sum), center C, gh[i].
#define OUT_ROW(i, BOX, C) do {                                         \
        float _fn[4];                                                   \
        const float* _b = (const float*)&(BOX);                         \
        const float* _c = (const float*)&(C);                           \
        const float* _g = (const float*)&gh[i];                         \
        _Pragma("unroll")                                               \
        for (int _j = 0; _j < 4; ++_j) {                                \
            const float _d = clamp01(_b[_j]);                           \
            const float _z = fmaf(10.0f, _d, fmaf(-10.0f, _c[_j], -5.0f)); \
            const float _t = tanh_fast(_z);                             \
            _fn[_j] = fmaf(_g[_j], _t, _g[_j]);                         \
            fn_iter += _fn[_j];                                         \
        }                                                               \
        if (k < NITER) {                                                \
            const int _pr = 1 + 4 * ty + (i);                           \
            if (_pr >= k && _pr <= 65 - k) {                            \
                float* _dst = nxt + _pr * SSTR + 4 + pc0;               \
                const float _p0 = _c[0] + _fn[0];                       \
                const float _p1 = _c[1] + _fn[1];                       \
                const float _p2 = _c[2] + _fn[2];                       \
                const float _p3 = _c[3] + _fn[3];                       \
                if (pc0 >= k - 1 && pc0 + 3 <= 64 - k) {                \
                    *(float4*)_dst = make_float4(_p0, _p1, _p2, _p3);   \
                } else {                                                \
                    if (pc0 + 0 >= k - 1 && pc0 + 0 <= 64 - k) _dst[0] = _p0; \
                    if (pc0 + 1 >= k - 1 && pc0 + 1 <= 64 - k) _dst[1] = _p1; \
                    if (pc0 + 2 >= k - 1 && pc0 + 2 <= 64 - k) _dst[2] = _p2; \
                    if (pc0 + 3 >= k - 1 && pc0 + 3 <= 64 - k) _dst[3] = _p3; \
                }                                                       \
            }                                                           \
        }                                                               \
    } while (0)

    #pragma unroll
    for (int k = 1; k <= NITER; ++k) {
        float fn_iter = 0.0f;
        float4 h0, h1, h2, h3, h4, h5, s;
        float4 c1, c2, c3, c4, cjunk;

        LOAD_ROW(0, h0, cjunk);
        LOAD_ROW(1, h1, c1);
        LOAD_ROW(2, h2, c2);
        s = add4(h1, h2);
        { float4 box = add4(h0, s);  OUT_ROW(0, box, c1); }

        LOAD_ROW(3, h3, c3);
        { float4 box = add4(s, h3);  OUT_ROW(1, box, c2); }

        LOAD_ROW(4, h4, c4);
        s = add4(h3, h4);
        { float4 box = add4(h2, s);  OUT_ROW(2, box, c3); }

        LOAD_ROW(5, h5, cjunk);
        { float4 box = add4(s, h5);  OUT_ROW(3, box, c4); }

        if (owner) wacc += wts[k - 1] * fn_iter;

        if (k < NITER) {
            __syncthreads();
            float* t = cur; cur = nxt; nxt = t;
        }
    }

#undef LOAD_ROW
#undef OUT_ROW

    // ---- block reduction, one atomic each per block; last block finalizes
    #pragma unroll
    for (int o = 16; o > 0; o >>= 1) {
        wacc     += __shfl_down_sync(0xffffffffu, wacc, o);
        gt_local += __shfl_down_sync(0xffffffffu, gt_local, o);
    }
    const int lane = tid & 31;
    const int wid  = tid >> 5;
    if (lane == 0) { red_w[wid] = wacc; red_g[wid] = gt_local; }
    __syncthreads();
    if (tid == 0) {
        float v = 0.0f, g = 0.0f;
        #pragma unroll
        for (int i = 0; i < 8; ++i) { v += red_w[i]; g += red_g[i]; }
        atomicAdd(&g_sums[1], v);
        atomicAdd(&g_sums[0], g);
        __threadfence();
        const unsigned int done = atomicAdd(&g_count, 1u);
        if (done == NBLK - 1) {
            const float s1 = atomicAdd(&g_sums[1], 0.0f);
            const float s0 = atomicAdd(&g_sums[0], 0.0f);
            out[0] = s1 / s0;
            g_sums[0] = 0.0f;
            g_sums[1] = 0.0f;
            g_count   = 0u;
        }
    }
}

extern "C" void kernel_launch(void* const* d_in, const int* in_sizes, int n_in,
                              void* d_out, int out_size) {
    (void)in_sizes; (void)n_in; (void)out_size;
    const float* pred = (const float*)d_in[0];
    const float* gt   = (const float*)d_in[1];
    float* out        = (float*)d_out;

    dim3 block(16, 16);
    dim3 grid(NTILES, NTILES);
    fused_kernel<<<grid, block>>>(pred, gt, out);
}

// round 8
// speedup vs baseline: 2.7580x; 1.6431x over previous
#include <cuda_runtime.h>

#define IMG 4096
#define TILE 56            // owned pixels per tile (both dims)
#define NROWS 66           // smem rows (input halo 5)
#define SSTR 72            // smem row stride in floats (= 18 float4)
#define NITER 5
#define NTILES ((IMG + TILE - 1) / TILE)     // 74
#define NBLK (NTILES * NTILES)               // 5476

// [0] = gt_sum, [1] = weighted fn sum  (reset by the last block each run)
__device__ float g_sums[2];
__device__ unsigned int g_count;

__device__ __forceinline__ float tanh_fast(float x) {
    float r; asm("tanh.approx.f32 %0, %1;" : "=f"(r) : "f"(x)); return r;
}
__device__ __forceinline__ float clamp01(float x) {
    return fminf(fmaxf(x, 0.0f), 1.0f);
}
__device__ __forceinline__ float4 add4(float4 a, float4 b) {
    return make_float4(a.x + b.x, a.y + b.y, a.z + b.z, a.w + b.w);
}
__device__ __forceinline__ float4 hsum3v(float l, float4 c, float rr) {
    const float pxy = c.x + c.y;
    const float pzw = c.z + c.w;
    return make_float4(l + pxy, pxy + c.z, c.y + pzw, pzw + rr);
}

__global__ void __launch_bounds__(256, 4)
fused_kernel(const float* __restrict__ pred, const float* __restrict__ gt,
             float* __restrict__ out) {
    __shared__ float sA[NROWS * SSTR];
    __shared__ float red_w[8], red_g[8];

    const int tx  = threadIdx.x;            // 0..15
    const int ty  = threadIdx.y;            // 0..15
    const int tid = ty * 16 + tx;

    const int gx0b = blockIdx.x * TILE - 8;  // 16B-aligned window start
    const int gy0  = blockIdx.y * TILE - 5;

    // ---- vectorized fill: 66 rows x 18 float4 (zero-pad OOB)
    for (int e = tid; e < NROWS * 18; e += 256) {
        const int r  = e / 18;
        const int ci = e - r * 18;
        const int gy = gy0 + r;
        const int gx = gx0b + 4 * ci;
        float4 v = make_float4(0.f, 0.f, 0.f, 0.f);
        if ((unsigned)gy < (unsigned)IMG && (unsigned)gx <= (unsigned)(IMG - 4))
            v = *(const float4*)(pred + (size_t)gy * IMG + gx);
        *(float4*)&sA[r * SSTR + 4 * ci] = v;
    }

    // ---- gt for this thread's 4x4 patch; keep gh = 0.5*g
    const bool owner = (tx >= 1) && (tx < 15) && (ty >= 1) && (ty < 15);
    const int gxp = gx0b + 4 + 4 * tx;
    float4 gh[4];
    float gt_local = 0.0f;
    #pragma unroll
    for (int i = 0; i < 4; ++i) {
        const int gy = gy0 + 1 + 4 * ty + i;
        float4 g = make_float4(0.f, 0.f, 0.f, 0.f);
        if ((unsigned)gy < (unsigned)IMG) {
            if (gxp >= 0 && gxp + 3 < IMG) {
                g = *(const float4*)(gt + (size_t)gy * IMG + gxp);
            } else {
                const float* row = gt + (size_t)gy * IMG;
                if ((unsigned)(gxp + 0) < (unsigned)IMG) g.x = row[gxp + 0];
                if ((unsigned)(gxp + 1) < (unsigned)IMG) g.y = row[gxp + 1];
                if ((unsigned)(gxp + 2) < (unsigned)IMG) g.z = row[gxp + 2];
                if ((unsigned)(gxp + 3) < (unsigned)IMG) g.w = row[gxp + 3];
            }
        }
        gt_local += (g.x + g.y) + (g.z + g.w);
        gh[i] = make_float4(0.5f * g.x, 0.5f * g.y, 0.5f * g.z, 0.5f * g.w);
    }
    if (!owner) gt_local = 0.0f;

    __syncthreads();

    const float wts[NITER] = {1.0f, 4.0f, 9.0f, 16.0f, 25.0f};
    float wacc = 0.0f;

    const bool is_l = (tx == 0);
    const bool is_r = (tx == 15);
    const int r0 = 4 * ty;                    // smem row of halo_top
    const int col = 4 + 4 * tx;               // smem col of patch start

    // horizontal 3-tap with edge handling; exact edges only needed at k==1
    auto hrow = [&](float4 c, int smemrow, bool edge_exact) -> float4 {
        const float lw = __shfl_up_sync(0xffffffffu, c.w, 1);
        const float rx = __shfl_down_sync(0xffffffffu, c.x, 1);
        float l = lw, rr = rx;
        if (edge_exact) {
            if (is_l) l  = sA[smemrow * SSTR + 3];   // logical col -1 (initial)
            if (is_r) rr = sA[smemrow * SSTR + 68];  // logical col 64 (initial)
        }
        return hsum3v(l, c, rr);
    };

    // per-pixel-row: fn from box/center/gh; accumulate; return fn
    auto pixrow = [](float4 b, float4 c, float4 g, float& acc) -> float4 {
        float4 fn;
        {
            float d, z, t;
            d = clamp01(b.x); z = fmaf(10.0f, d, fmaf(-10.0f, c.x, -5.0f));
            t = tanh_fast(z); fn.x = fmaf(g.x, t, g.x);
            d = clamp01(b.y); z = fmaf(10.0f, d, fmaf(-10.0f, c.y, -5.0f));
            t = tanh_fast(z); fn.y = fmaf(g.y, t, g.y);
            d = clamp01(b.z); z = fmaf(10.0f, d, fmaf(-10.0f, c.z, -5.0f));
            t = tanh_fast(z); fn.z = fmaf(g.z, t, g.z);
            d = clamp01(b.w); z = fmaf(10.0f, d, fmaf(-10.0f, c.w, -5.0f));
            t = tanh_fast(z); fn.w = fmaf(g.w, t, g.w);
        }
        acc += (fn.x + fn.y) + (fn.z + fn.w);
        return fn;
    };

    // ---- preload own 4 rows into registers
    float4 c1 = *(const float4*)&sA[(r0 + 1) * SSTR + col];
    float4 c2 = *(const float4*)&sA[(r0 + 2) * SSTR + col];
    float4 c3 = *(const float4*)&sA[(r0 + 3) * SSTR + col];
    float4 c4 = *(const float4*)&sA[(r0 + 4) * SSTR + col];

    #pragma unroll
    for (int k = 1; k <= NITER; ++k) {
        const bool ex = (k == 1);
        // vertical halo rows from smem
        const float4 htop = *(const float4*)&sA[(r0 + 0) * SSTR + col];
        const float4 hbot = *(const float4*)&sA[(r0 + 5) * SSTR + col];

        const float4 h0 = hrow(htop, r0 + 0, ex);
        const float4 h1 = hrow(c1,   r0 + 1, ex);
        const float4 h2 = hrow(c2,   r0 + 2, ex);
        const float4 h3 = hrow(c3,   r0 + 3, ex);
        const float4 h4 = hrow(c4,   r0 + 4, ex);
        const float4 h5 = hrow(hbot, r0 + 5, ex);

        const float4 s12 = add4(h1, h2);
        const float4 s34 = add4(h3, h4);
        const float4 b0 = add4(h0, s12);
        const float4 b1 = add4(s12, h3);
        const float4 b2 = add4(h2, s34);
        const float4 b3 = add4(s34, h5);

        float fn_iter = 0.0f;
        const float4 f0 = pixrow(b0, c1, gh[0], fn_iter);
        const float4 f1 = pixrow(b1, c2, gh[1], fn_iter);
        const float4 f2 = pixrow(b2, c3, gh[2], fn_iter);
        const float4 f3 = pixrow(b3, c4, gh[3], fn_iter);

        if (owner) wacc += wts[k - 1] * fn_iter;

        if (k < NITER) {
            c1 = add4(c1, f0);
            c2 = add4(c2, f1);
            c3 = add4(c3, f2);
            c4 = add4(c4, f3);
            __syncthreads();                       // all halo reads done
            *(float4*)&sA[(r0 + 1) * SSTR + col] = c1;
            *(float4*)&sA[(r0 + 4) * SSTR + col] = c4;
            __syncthreads();                       // writes visible
        }
    }

    // ---- block reduction, one atomic each per block; last block finalizes
    #pragma unroll
    for (int o = 16; o > 0; o >>= 1) {
        wacc     += __shfl_down_sync(0xffffffffu, wacc, o);
        gt_local += __shfl_down_sync(0xffffffffu, gt_local, o);
    }
    const int lane = tid & 31;
    const int wid  = tid >> 5;
    if (lane == 0) { red_w[wid] = wacc; red_g[wid] = gt_local; }
    __syncthreads();
    if (tid == 0) {
        float v = 0.0f, g = 0.0f;
        #pragma unroll
        for (int i = 0; i < 8; ++i) { v += red_w[i]; g += red_g[i]; }
        atomicAdd(&g_sums[1], v);
        atomicAdd(&g_sums[0], g);
        __threadfence();
        const unsigned int done = atomicAdd(&g_count, 1u);
        if (done == NBLK - 1) {
            const float s1 = atomicAdd(&g_sums[1], 0.0f);
            const float s0 = atomicAdd(&g_sums[0], 0.0f);
            out[0] = s1 / s0;
            g_sums[0] = 0.0f;
            g_sums[1] = 0.0f;
            g_count   = 0u;
        }
    }
}

extern "C" void kernel_launch(void* const* d_in, const int* in_sizes, int n_in,
                              void* d_out, int out_size) {
    (void)in_sizes; (void)n_in; (void)out_size;
    const float* pred = (const float*)d_in[0];
    const float* gt   = (const float*)d_in[1];
    float* out        = (float*)d_out;

    dim3 block(16, 16);
    dim3 grid(NTILES, NTILES);
    fused_kernel<<<grid, block>>>(pred, gt, out);
}

// round 9
// speedup vs baseline: 2.7592x; 1.0004x over previous
#include <cuda_runtime.h>

#define IMG 4096
#define TILE 56            // owned pixels per tile (both dims)
#define NROWS 66           // smem rows (input halo 5)
#define SSTR 72            // smem row stride in floats (= 18 float4)
#define NITER 5
#define NTILES ((IMG + TILE - 1) / TILE)     // 74
#define NBLK (NTILES * NTILES)               // 5476

// [0] = gt_sum, [1] = weighted fn sum  (reset by the last block each run)
__device__ float g_sums[2];
__device__ unsigned int g_count;

__device__ __forceinline__ float tanh_fast(float x) {
    float r; asm("tanh.approx.f32 %0, %1;" : "=f"(r) : "f"(x)); return r;
}
// add with saturation to [0,1] — matches clip(a+b, 0, 1) for finite data
__device__ __forceinline__ float addsat(float a, float b) {
    float r; asm("add.rn.sat.f32 %0, %1, %2;" : "=f"(r) : "f"(a), "f"(b)); return r;
}
__device__ __forceinline__ float4 add4(float4 a, float4 b) {
    return make_float4(a.x + b.x, a.y + b.y, a.z + b.z, a.w + b.w);
}
__device__ __forceinline__ float4 addsat4(float4 a, float4 b) {
    return make_float4(addsat(a.x, b.x), addsat(a.y, b.y),
                       addsat(a.z, b.z), addsat(a.w, b.w));
}
__device__ __forceinline__ float4 hsum3v(float l, float4 c, float rr) {
    const float pxy = c.x + c.y;
    const float pzw = c.z + c.w;
    return make_float4(l + pxy, pxy + c.z, c.y + pzw, pzw + rr);
}

__global__ void __launch_bounds__(256, 4)
fused_kernel(const float* __restrict__ pred, const float* __restrict__ gt,
             float* __restrict__ out) {
    __shared__ float sA[NROWS * SSTR];          // initial pred (read-only after fill)
    __shared__ float hb[2][32 * SSTR];          // halo row ping-pong
    __shared__ float red_w[8], red_g[8];

    const int tx  = threadIdx.x;            // 0..15
    const int ty  = threadIdx.y;            // 0..15
    const int tid = ty * 16 + tx;

    const int gx0b = blockIdx.x * TILE - 8;  // 16B-aligned window start
    const int gy0  = blockIdx.y * TILE - 5;

    // ---- vectorized fill: 66 rows x 18 float4 (zero-pad OOB)
    for (int e = tid; e < NROWS * 18; e += 256) {
        const int r  = e / 18;
        const int ci = e - r * 18;
        const int gy = gy0 + r;
        const int gx = gx0b + 4 * ci;
        float4 v = make_float4(0.f, 0.f, 0.f, 0.f);
        if ((unsigned)gy < (unsigned)IMG && (unsigned)gx <= (unsigned)(IMG - 4))
            v = *(const float4*)(pred + (size_t)gy * IMG + gx);
        *(float4*)&sA[r * SSTR + 4 * ci] = v;
    }

    // ---- gt for this thread's 4x4 patch; keep gh = 0.5*g
    const bool owner = (tx >= 1) && (tx < 15) && (ty >= 1) && (ty < 15);
    const int gxp = gx0b + 4 + 4 * tx;
    float4 gh[4];
    float gt_local = 0.0f;
    #pragma unroll
    for (int i = 0; i < 4; ++i) {
        const int gy = gy0 + 1 + 4 * ty + i;
        float4 g = make_float4(0.f, 0.f, 0.f, 0.f);
        if ((unsigned)gy < (unsigned)IMG) {
            if (gxp >= 0 && gxp + 3 < IMG) {
                g = *(const float4*)(gt + (size_t)gy * IMG + gxp);
            } else {
                const float* row = gt + (size_t)gy * IMG;
                if ((unsigned)(gxp + 0) < (unsigned)IMG) g.x = row[gxp + 0];
                if ((unsigned)(gxp + 1) < (unsigned)IMG) g.y = row[gxp + 1];
                if ((unsigned)(gxp + 2) < (unsigned)IMG) g.z = row[gxp + 2];
                if ((unsigned)(gxp + 3) < (unsigned)IMG) g.w = row[gxp + 3];
            }
        }
        gt_local += (g.x + g.y) + (g.z + g.w);
        gh[i] = make_float4(0.5f * g.x, 0.5f * g.y, 0.5f * g.z, 0.5f * g.w);
    }
    if (!owner) gt_local = 0.0f;

    __syncthreads();

    const float wts[NITER] = {1.0f, 4.0f, 9.0f, 16.0f, 25.0f};
    float wacc = 0.0f;

    const bool is_l = (tx == 0);
    const bool is_r = (tx == 15);
    const int r0  = 4 * ty;                   // smem row of halo_top (sA space)
    const int col = 4 + 4 * tx;               // smem col of patch start
    // compact halo slots: own row1 -> 2ty, own row4 -> 2ty+1
    const int slot_top = (ty > 0)  ? (2 * ty - 1) : 0;    // (ty-1)'s row4
    const int slot_bot = (ty < 15) ? (2 * ty + 2) : 31;   // (ty+1)'s row1

    // horizontal 3-tap; exact edges only needed at k==1 (from pristine sA)
    auto hrow = [&](float4 c, int smemrow, bool edge_exact) -> float4 {
        const float lw = __shfl_up_sync(0xffffffffu, c.w, 1);
        const float rx = __shfl_down_sync(0xffffffffu, c.x, 1);
        float l = lw, rr = rx;
        if (edge_exact) {
            if (is_l) l  = sA[smemrow * SSTR + 3];   // logical col -1
            if (is_r) rr = sA[smemrow * SSTR + 68];  // logical col 64
        }
        return hsum3v(l, c, rr);
    };

    // per-pixel-row: fn from saturated box d, center c, gh
    auto pixrow = [](float4 d, float4 c, float4 g, float& acc) -> float4 {
        float4 fn;
        {
            float z, t;
            z = fmaf(10.0f, d.x, fmaf(-10.0f, c.x, -5.0f));
            t = tanh_fast(z); fn.x = fmaf(g.x, t, g.x);
            z = fmaf(10.0f, d.y, fmaf(-10.0f, c.y, -5.0f));
            t = tanh_fast(z); fn.y = fmaf(g.y, t, g.y);
            z = fmaf(10.0f, d.z, fmaf(-10.0f, c.z, -5.0f));
            t = tanh_fast(z); fn.z = fmaf(g.z, t, g.z);
            z = fmaf(10.0f, d.w, fmaf(-10.0f, c.w, -5.0f));
            t = tanh_fast(z); fn.w = fmaf(g.w, t, g.w);
        }
        acc += (fn.x + fn.y) + (fn.z + fn.w);
        return fn;
    };

    // ---- preload own 4 rows into registers
    float4 c1 = *(const float4*)&sA[(r0 + 1) * SSTR + col];
    float4 c2 = *(const float4*)&sA[(r0 + 2) * SSTR + col];
    float4 c3 = *(const float4*)&sA[(r0 + 3) * SSTR + col];
    float4 c4 = *(const float4*)&sA[(r0 + 4) * SSTR + col];

    #pragma unroll
    for (int k = 1; k <= NITER; ++k) {
        const bool ex = (k == 1);
        float4 htop, hbot;
        if (ex) {
            htop = *(const float4*)&sA[(r0 + 0) * SSTR + col];
            hbot = *(const float4*)&sA[(r0 + 5) * SSTR + col];
        } else {
            const float* hsrc = hb[(k - 1) & 1];
            htop = *(const float4*)&hsrc[slot_top * SSTR + col];
            hbot = *(const float4*)&hsrc[slot_bot * SSTR + col];
        }

        const float4 h0 = hrow(htop, r0 + 0, ex);
        const float4 h1 = hrow(c1,   r0 + 1, ex);
        const float4 h2 = hrow(c2,   r0 + 2, ex);
        const float4 h3 = hrow(c3,   r0 + 3, ex);
        const float4 h4 = hrow(c4,   r0 + 4, ex);
        const float4 h5 = hrow(hbot, r0 + 5, ex);

        const float4 s12 = add4(h1, h2);
        const float4 s34 = add4(h3, h4);
        const float4 d0 = addsat4(h0, s12);     // = clip(box, 0, 1)
        const float4 d1 = addsat4(s12, h3);
        const float4 d2 = addsat4(h2, s34);
        const float4 d3 = addsat4(s34, h5);

        float fn_iter = 0.0f;
        const float4 f0 = pixrow(d0, c1, gh[0], fn_iter);
        const float4 f1 = pixrow(d1, c2, gh[1], fn_iter);
        const float4 f2 = pixrow(d2, c3, gh[2], fn_iter);
        const float4 f3 = pixrow(d3, c4, gh[3], fn_iter);

        if (owner) wacc += wts[k - 1] * fn_iter;

        if (k < NITER) {
            c1 = add4(c1, f0);
            c2 = add4(c2, f1);
            c3 = add4(c3, f2);
            c4 = add4(c4, f3);
            float* hdst = hb[k & 1];
            *(float4*)&hdst[(2 * ty + 0) * SSTR + col] = c1;
            *(float4*)&hdst[(2 * ty + 1) * SSTR + col] = c4;
            __syncthreads();                   // writes visible for next iter
        }
    }

    // ---- block reduction, one atomic each per block; last block finalizes
    #pragma unroll
    for (int o = 16; o > 0; o >>= 1) {
        wacc     += __shfl_down_sync(0xffffffffu, wacc, o);
        gt_local += __shfl_down_sync(0xffffffffu, gt_local, o);
    }
    const int lane = tid & 31;
    const int wid  = tid >> 5;
    if (lane == 0) { red_w[wid] = wacc; red_g[wid] = gt_local; }
    __syncthreads();
    if (tid == 0) {
        float v = 0.0f, g = 0.0f;
        #pragma unroll
        for (int i = 0; i < 8; ++i) { v += red_w[i]; g += red_g[i]; }
        atomicAdd(&g_sums[1], v);
        atomicAdd(&g_sums[0], g);
        __threadfence();
        const unsigned int done = atomicAdd(&g_count, 1u);
        if (done == NBLK - 1) {
            const float s1 = atomicAdd(&g_sums[1], 0.0f);
            const float s0 = atomicAdd(&g_sums[0], 0.0f);
            out[0] = s1 / s0;
            g_sums[0] = 0.0f;
            g_sums[1] = 0.0f;
            g_count   = 0u;
        }
    }
}

extern "C" void kernel_launch(void* const* d_in, const int* in_sizes, int n_in,
                              void* d_out, int out_size) {
    (void)in_sizes; (void)n_in; (void)out_size;
    const float* pred = (const float*)d_in[0];
    const float* gt   = (const float*)d_in[1];
    float* out        = (float*)d_out;

    dim3 block(16, 16);
    dim3 grid(NTILES, NTILES);
    fused_kernel<<<grid, block>>>(pred, gt, out);
}

// round 10
// speedup vs baseline: 2.9015x; 1.0516x over previous
#include <cuda_runtime.h>

#define IMG 4096
#define TILE 56            // owned pixels per tile (both dims)
#define NROWS 66           // smem rows (input halo 5)
#define SSTR 72            // smem row stride in floats (= 18 float4)
#define NITER 5
#define NTILES ((IMG + TILE - 1) / TILE)     // 74
#define NBLK (NTILES * NTILES)               // 5476

// [0] = gt_sum, [1] = weighted fn sum  (reset by the last block each run)
__device__ float g_sums[2];
__device__ unsigned int g_count;

__device__ __forceinline__ float tanh_fast(float x) {
    float r; asm("tanh.approx.f32 %0, %1;" : "=f"(r) : "f"(x)); return r;
}
// add with saturation to [0,1] — matches clip(a+b, 0, 1) for finite data
__device__ __forceinline__ float addsat(float a, float b) {
    float r; asm("add.rn.sat.f32 %0, %1, %2;" : "=f"(r) : "f"(a), "f"(b)); return r;
}
__device__ __forceinline__ float4 add4(float4 a, float4 b) {
    return make_float4(a.x + b.x, a.y + b.y, a.z + b.z, a.w + b.w);
}
// horizontal 3-tap on a vertical-sum row, with clip fused into the last add
__device__ __forceinline__ float4 hfin(float l, float4 v, float rr) {
    const float pxy = v.x + v.y;
    const float pzw = v.z + v.w;
    return make_float4(addsat(l, pxy), addsat(pxy, v.z),
                       addsat(v.y, pzw), addsat(pzw, rr));
}

__global__ void __launch_bounds__(256, 4)
fused_kernel(const float* __restrict__ pred, const float* __restrict__ gt,
             float* __restrict__ out) {
    __shared__ float sA[NROWS * SSTR];          // initial pred (read-only after fill)
    __shared__ float hb[2][32 * SSTR];          // halo row ping-pong
    __shared__ float red_w[8], red_g[8];

    const int tx  = threadIdx.x;            // 0..15
    const int ty  = threadIdx.y;            // 0..15
    const int tid = ty * 16 + tx;

    const int gx0b = blockIdx.x * TILE - 8;  // 16B-aligned window start
    const int gy0  = blockIdx.y * TILE - 5;

    // ---- vectorized fill: 66 rows x 18 float4 (zero-pad OOB)
    for (int e = tid; e < NROWS * 18; e += 256) {
        const int r  = e / 18;
        const int ci = e - r * 18;
        const int gy = gy0 + r;
        const int gx = gx0b + 4 * ci;
        float4 v = make_float4(0.f, 0.f, 0.f, 0.f);
        if ((unsigned)gy < (unsigned)IMG && (unsigned)gx <= (unsigned)(IMG - 4))
            v = *(const float4*)(pred + (size_t)gy * IMG + gx);
        *(float4*)&sA[r * SSTR + 4 * ci] = v;
    }

    // ---- gt for this thread's 4x4 patch; keep gh = 0.5*g
    const bool owner = (tx >= 1) && (tx < 15) && (ty >= 1) && (ty < 15);
    const int gxp = gx0b + 4 + 4 * tx;
    float4 gh[4];
    float gt_local = 0.0f;
    #pragma unroll
    for (int i = 0; i < 4; ++i) {
        const int gy = gy0 + 1 + 4 * ty + i;
        float4 g = make_float4(0.f, 0.f, 0.f, 0.f);
        if ((unsigned)gy < (unsigned)IMG) {
            if (gxp >= 0 && gxp + 3 < IMG) {
                g = *(const float4*)(gt + (size_t)gy * IMG + gxp);
            } else {
                const float* row = gt + (size_t)gy * IMG;
                if ((unsigned)(gxp + 0) < (unsigned)IMG) g.x = row[gxp + 0];
                if ((unsigned)(gxp + 1) < (unsigned)IMG) g.y = row[gxp + 1];
                if ((unsigned)(gxp + 2) < (unsigned)IMG) g.z = row[gxp + 2];
                if ((unsigned)(gxp + 3) < (unsigned)IMG) g.w = row[gxp + 3];
            }
        }
        gt_local += (g.x + g.y) + (g.z + g.w);
        gh[i] = make_float4(0.5f * g.x, 0.5f * g.y, 0.5f * g.z, 0.5f * g.w);
    }
    if (!owner) gt_local = 0.0f;

    __syncthreads();

    const float wts[NITER] = {1.0f, 4.0f, 9.0f, 16.0f, 25.0f};
    float wacc = 0.0f;

    const bool is_l = (tx == 0);
    const bool is_r = (tx == 15);
    const int r0  = 4 * ty;
    const int col = 4 + 4 * tx;
    const int slot_top = (ty > 0)  ? (2 * ty - 1) : 0;    // (ty-1)'s row4
    const int slot_bot = (ty < 15) ? (2 * ty + 2) : 31;   // (ty+1)'s row1

    // fn for one pixel row from clipped box d, center c, gh
    auto pixrow = [](float4 d, float4 c, float4 g, float& acc) -> float4 {
        float4 fn;
        float z, t;
        z = fmaf(10.0f, d.x, fmaf(-10.0f, c.x, -5.0f));
        t = tanh_fast(z); fn.x = fmaf(g.x, t, g.x);
        z = fmaf(10.0f, d.y, fmaf(-10.0f, c.y, -5.0f));
        t = tanh_fast(z); fn.y = fmaf(g.y, t, g.y);
        z = fmaf(10.0f, d.z, fmaf(-10.0f, c.z, -5.0f));
        t = tanh_fast(z); fn.z = fmaf(g.z, t, g.z);
        z = fmaf(10.0f, d.w, fmaf(-10.0f, c.w, -5.0f));
        t = tanh_fast(z); fn.w = fmaf(g.w, t, g.w);
        acc += (fn.x + fn.y) + (fn.z + fn.w);
        return fn;
    };

    // ---- preload own 4 rows into registers
    float4 c1 = *(const float4*)&sA[(r0 + 1) * SSTR + col];
    float4 c2 = *(const float4*)&sA[(r0 + 2) * SSTR + col];
    float4 c3 = *(const float4*)&sA[(r0 + 3) * SSTR + col];
    float4 c4 = *(const float4*)&sA[(r0 + 4) * SSTR + col];

    // ================= k = 1 (peeled; exact edges from pristine sA) ========
    {
        const float4 htop = *(const float4*)&sA[(r0 + 0) * SSTR + col];
        const float4 hbot = *(const float4*)&sA[(r0 + 5) * SSTR + col];

        const float4 s12 = add4(c1, c2);
        const float4 s34 = add4(c3, c4);
        const float4 v0 = add4(htop, s12);
        const float4 v1 = add4(s12, c3);
        const float4 v2 = add4(c2, s34);
        const float4 v3 = add4(s34, hbot);

        // exact edge vertical sums (2 lanes only)
        float vl0, vl1, vl2, vl3, vr0, vr1, vr2, vr3;
        if (is_l) {
            const float e0 = sA[(r0 + 0) * SSTR + 3];
            const float e1 = sA[(r0 + 1) * SSTR + 3];
            const float e2 = sA[(r0 + 2) * SSTR + 3];
            const float e3 = sA[(r0 + 3) * SSTR + 3];
            const float e4 = sA[(r0 + 4) * SSTR + 3];
            const float e5 = sA[(r0 + 5) * SSTR + 3];
            const float q12 = e1 + e2, q34 = e3 + e4;
            vl0 = e0 + q12; vl1 = q12 + e3; vl2 = e2 + q34; vl3 = q34 + e5;
        }
        if (is_r) {
            const float e0 = sA[(r0 + 0) * SSTR + 68];
            const float e1 = sA[(r0 + 1) * SSTR + 68];
            const float e2 = sA[(r0 + 2) * SSTR + 68];
            const float e3 = sA[(r0 + 3) * SSTR + 68];
            const float e4 = sA[(r0 + 4) * SSTR + 68];
            const float e5 = sA[(r0 + 5) * SSTR + 68];
            const float q12 = e1 + e2, q34 = e3 + e4;
            vr0 = e0 + q12; vr1 = q12 + e3; vr2 = e2 + q34; vr3 = q34 + e5;
        }

        float l, rr;
        float fn_iter = 0.0f;

        l  = __shfl_up_sync(0xffffffffu, v0.w, 1);
        rr = __shfl_down_sync(0xffffffffu, v0.x, 1);
        if (is_l) l = vl0;
        if (is_r) rr = vr0;
        const float4 f0 = pixrow(hfin(l, v0, rr), c1, gh[0], fn_iter);

        l  = __shfl_up_sync(0xffffffffu, v1.w, 1);
        rr = __shfl_down_sync(0xffffffffu, v1.x, 1);
        if (is_l) l = vl1;
        if (is_r) rr = vr1;
        const float4 f1 = pixrow(hfin(l, v1, rr), c2, gh[1], fn_iter);

        l  = __shfl_up_sync(0xffffffffu, v2.w, 1);
        rr = __shfl_down_sync(0xffffffffu, v2.x, 1);
        if (is_l) l = vl2;
        if (is_r) rr = vr2;
        const float4 f2 = pixrow(hfin(l, v2, rr), c3, gh[2], fn_iter);

        l  = __shfl_up_sync(0xffffffffu, v3.w, 1);
        rr = __shfl_down_sync(0xffffffffu, v3.x, 1);
        if (is_l) l = vl3;
        if (is_r) rr = vr3;
        const float4 f3 = pixrow(hfin(l, v3, rr), c4, gh[3], fn_iter);

        if (owner) wacc += wts[0] * fn_iter;

        c1 = add4(c1, f0);
        c2 = add4(c2, f1);
        c3 = add4(c3, f2);
        c4 = add4(c4, f3);
        float* hdst = hb[1];
        *(float4*)&hdst[(2 * ty + 0) * SSTR + col] = c1;
        *(float4*)&hdst[(2 * ty + 1) * SSTR + col] = c4;
        __syncthreads();
    }

    // ================= k = 2..5 (no edge handling) =========================
    #pragma unroll
    for (int k = 2; k <= NITER; ++k) {
        const float* hsrc = hb[(k - 1) & 1];
        const float4 htop = *(const float4*)&hsrc[slot_top * SSTR + col];
        const float4 hbot = *(const float4*)&hsrc[slot_bot * SSTR + col];

        const float4 s12 = add4(c1, c2);
        const float4 s34 = add4(c3, c4);
        const float4 v0 = add4(htop, s12);
        const float4 v1 = add4(s12, c3);
        const float4 v2 = add4(c2, s34);
        const float4 v3 = add4(s34, hbot);

        float fn_iter = 0.0f;
        const float4 f0 = pixrow(
            hfin(__shfl_up_sync(0xffffffffu, v0.w, 1), v0,
                 __shfl_down_sync(0xffffffffu, v0.x, 1)), c1, gh[0], fn_iter);
        const float4 f1 = pixrow(
            hfin(__shfl_up_sync(0xffffffffu, v1.w, 1), v1,
                 __shfl_down_sync(0xffffffffu, v1.x, 1)), c2, gh[1], fn_iter);
        const float4 f2 = pixrow(
            hfin(__shfl_up_sync(0xffffffffu, v2.w, 1), v2,
                 __shfl_down_sync(0xffffffffu, v2.x, 1)), c3, gh[2], fn_iter);
        const float4 f3 = pixrow(
            hfin(__shfl_up_sync(0xffffffffu, v3.w, 1), v3,
                 __shfl_down_sync(0xffffffffu, v3.x, 1)), c4, gh[3], fn_iter);

        if (owner) wacc += wts[k - 1] * fn_iter;

        if (k < NITER) {
            c1 = add4(c1, f0);
            c2 = add4(c2, f1);
            c3 = add4(c3, f2);
            c4 = add4(c4, f3);
            float* hdst = hb[k & 1];
            *(float4*)&hdst[(2 * ty + 0) * SSTR + col] = c1;
            *(float4*)&hdst[(2 * ty + 1) * SSTR + col] = c4;
            __syncthreads();
        }
    }

    // ---- block reduction, one atomic each per block; last block finalizes
    #pragma unroll
    for (int o = 16; o > 0; o >>= 1) {
        wacc     += __shfl_down_sync(0xffffffffu, wacc, o);
        gt_local += __shfl_down_sync(0xffffffffu, gt_local, o);
    }
    const int lane = tid & 31;
    const int wid  = tid >> 5;
    if (lane == 0) { red_w[wid] = wacc; red_g[wid] = gt_local; }
    __syncthreads();
    if (tid == 0) {
        float v = 0.0f, g = 0.0f;
        #pragma unroll
        for (int i = 0; i < 8; ++i) { v += red_w[i]; g += red_g[i]; }
        atomicAdd(&g_sums[1], v);
        atomicAdd(&g_sums[0], g);
        __threadfence();
        const unsigned int done = atomicAdd(&g_count, 1u);
        if (done == NBLK - 1) {
            const float s1 = atomicAdd(&g_sums[1], 0.0f);
            const float s0 = atomicAdd(&g_sums[0], 0.0f);
            out[0] = s1 / s0;
            g_sums[0] = 0.0f;
            g_sums[1] = 0.0f;
            g_count   = 0u;
        }
    }
}

extern "C" void kernel_launch(void* const* d_in, const int* in_sizes, int n_in,
                              void* d_out, int out_size) {
    (void)in_sizes; (void)n_in; (void)out_size;
    const float* pred = (const float*)d_in[0];
    const float* gt   = (const float*)d_in[1];
    float* out        = (float*)d_out;

    dim3 block(16, 16);
    dim3 grid(NTILES, NTILES);
    fused_kernel<<<grid, block>>>(pred, gt, out);
}

// round 11
// speedup vs baseline: 3.5471x; 1.2225x over previous
#include <cuda_runtime.h>

#define IMG 4096
#define TILE 56            // owned pixels per tile (both dims)
#define SSTR 72            // halo-row stride in floats
#define NITER 5
#define NTILES ((IMG + TILE - 1) / TILE)     // 74
#define NBLK (NTILES * NTILES)               // 5476

// [0] = gt_sum, [1] = weighted fn sum  (reset by the last block each run)
__device__ float g_sums[2];
__device__ unsigned int g_count;

__device__ __forceinline__ float tanh_fast(float x) {
    float r; asm("tanh.approx.f32 %0, %1;" : "=f"(r) : "f"(x)); return r;
}
// add with saturation to [0,1] — matches clip(a+b, 0, 1) for finite data
__device__ __forceinline__ float addsat(float a, float b) {
    float r; asm("add.rn.sat.f32 %0, %1, %2;" : "=f"(r) : "f"(a), "f"(b)); return r;
}
__device__ __forceinline__ float4 add4(float4 a, float4 b) {
    return make_float4(a.x + b.x, a.y + b.y, a.z + b.z, a.w + b.w);
}
// horizontal 3-tap on a vertical-sum row, with clip fused into the last add
__device__ __forceinline__ float4 hfin(float l, float4 v, float rr) {
    const float pxy = v.x + v.y;
    const float pzw = v.z + v.w;
    return make_float4(addsat(l, pxy), addsat(pxy, v.z),
                       addsat(v.y, pzw), addsat(pzw, rr));
}

__global__ void __launch_bounds__(256, 4)
fused_kernel(const float* __restrict__ pred, const float* __restrict__ gt,
             float* __restrict__ out) {
    __shared__ float hb[2][32 * SSTR];          // inter-iteration halo rows
    __shared__ float red_w[8], red_g[8];

    const int tx  = threadIdx.x;            // 0..15
    const int ty  = threadIdx.y;            // 0..15
    const int tid = ty * 16 + tx;

    const int gx0b = blockIdx.x * TILE - 8;  // window start (logical col 0 = +4)
    const int gy0  = blockIdx.y * TILE - 5;

    const bool is_l = (tx == 0);
    const bool is_r = (tx == 15);
    const int r0  = 4 * ty;
    const int col = 4 + 4 * tx;               // halo-buffer col of patch start
    const int slot_top = (ty > 0)  ? (2 * ty - 1) : 0;    // (ty-1)'s row4
    const int slot_bot = (ty < 15) ? (2 * ty + 2) : 31;   // (ty+1)'s row1

    // ---- direct global loads: 6 rows x float4 (zero-pad OOB)
    const int gxc = gx0b + col;               // global x of patch col 0
    const bool xok = (gxc >= 0) && (gxc <= IMG - 4);
    float4 rw[6];
    #pragma unroll
    for (int j = 0; j < 6; ++j) {
        const int gy = gy0 + r0 + j;
        float4 v = make_float4(0.f, 0.f, 0.f, 0.f);
        if (xok && (unsigned)gy < (unsigned)IMG)
            v = *(const float4*)(pred + (size_t)gy * IMG + gxc);
        rw[j] = v;
    }
    float4 c1 = rw[1], c2 = rw[2], c3 = rw[3], c4 = rw[4];

    // exact edge vertical sums for k=1 (2 lanes per half-warp only)
    float vl0, vl1, vl2, vl3, vr0, vr1, vr2, vr3;
    if (is_l) {
        const unsigned gxl = (unsigned)(gx0b + 3);   // logical col -1
        float e[6];
        #pragma unroll
        for (int j = 0; j < 6; ++j) {
            const int gy = gy0 + r0 + j;
            e[j] = ((unsigned)gy < (unsigned)IMG && gxl < (unsigned)IMG)
                       ? pred[(size_t)gy * IMG + gxl] : 0.0f;
        }
        const float q12 = e[1] + e[2], q34 = e[3] + e[4];
        vl0 = e[0] + q12; vl1 = q12 + e[3]; vl2 = e[2] + q34; vl3 = q34 + e[5];
    }
    if (is_r) {
        const unsigned gxr = (unsigned)(gx0b + 68);  // logical col 64
        float e[6];
        #pragma unroll
        for (int j = 0; j < 6; ++j) {
            const int gy = gy0 + r0 + j;
            e[j] = ((unsigned)gy < (unsigned)IMG && gxr < (unsigned)IMG)
                       ? pred[(size_t)gy * IMG + gxr] : 0.0f;
        }
        const float q12 = e[1] + e[2], q34 = e[3] + e[4];
        vr0 = e[0] + q12; vr1 = q12 + e[3]; vr2 = e[2] + q34; vr3 = q34 + e[5];
    }

    // ---- gt for this thread's 4x4 patch; keep gh = 0.5*g
    const bool owner = (tx >= 1) && (tx < 15) && (ty >= 1) && (ty < 15);
    float4 gh[4];
    float gt_local = 0.0f;
    #pragma unroll
    for (int i = 0; i < 4; ++i) {
        const int gy = gy0 + 1 + r0 + i;
        float4 g = make_float4(0.f, 0.f, 0.f, 0.f);
        if (xok && (unsigned)gy < (unsigned)IMG)
            g = *(const float4*)(gt + (size_t)gy * IMG + gxc);
        gt_local += (g.x + g.y) + (g.z + g.w);
        gh[i] = make_float4(0.5f * g.x, 0.5f * g.y, 0.5f * g.z, 0.5f * g.w);
    }
    if (!owner) gt_local = 0.0f;

    const float wts[NITER] = {1.0f, 4.0f, 9.0f, 16.0f, 25.0f};
    float wacc = 0.0f;

    // fn for one pixel row from clipped box d, center c, gh
    auto pixrow = [](float4 d, float4 c, float4 g, float& acc) -> float4 {
        float4 fn;
        float z, t;
        z = fmaf(10.0f, d.x, fmaf(-10.0f, c.x, -5.0f));
        t = tanh_fast(z); fn.x = fmaf(g.x, t, g.x);
        z = fmaf(10.0f, d.y, fmaf(-10.0f, c.y, -5.0f));
        t = tanh_fast(z); fn.y = fmaf(g.y, t, g.y);
        z = fmaf(10.0f, d.z, fmaf(-10.0f, c.z, -5.0f));
        t = tanh_fast(z); fn.z = fmaf(g.z, t, g.z);
        z = fmaf(10.0f, d.w, fmaf(-10.0f, c.w, -5.0f));
        t = tanh_fast(z); fn.w = fmaf(g.w, t, g.w);
        acc += (fn.x + fn.y) + (fn.z + fn.w);
        return fn;
    };

    // ================= k = 1 (no barrier needed; all inputs in registers) ==
    {
        const float4 s12 = add4(c1, c2);
        const float4 s34 = add4(c3, c4);
        const float4 v0 = add4(rw[0], s12);
        const float4 v1 = add4(s12, c3);
        const float4 v2 = add4(c2, s34);
        const float4 v3 = add4(s34, rw[5]);

        float l, rr;
        float fn_iter = 0.0f;

        l  = __shfl_up_sync(0xffffffffu, v0.w, 1);
        rr = __shfl_down_sync(0xffffffffu, v0.x, 1);
        if (is_l) l = vl0;
        if (is_r) rr = vr0;
        const float4 f0 = pixrow(hfin(l, v0, rr), c1, gh[0], fn_iter);

        l  = __shfl_up_sync(0xffffffffu, v1.w, 1);
        rr = __shfl_down_sync(0xffffffffu, v1.x, 1);
        if (is_l) l = vl1;
        if (is_r) rr = vr1;
        const float4 f1 = pixrow(hfin(l, v1, rr), c2, gh[1], fn_iter);

        l  = __shfl_up_sync(0xffffffffu, v2.w, 1);
        rr = __shfl_down_sync(0xffffffffu, v2.x, 1);
        if (is_l) l = vl2;
        if (is_r) rr = vr2;
        const float4 f2 = pixrow(hfin(l, v2, rr), c3, gh[2], fn_iter);

        l  = __shfl_up_sync(0xffffffffu, v3.w, 1);
        rr = __shfl_down_sync(0xffffffffu, v3.x, 1);
        if (is_l) l = vl3;
        if (is_r) rr = vr3;
        const float4 f3 = pixrow(hfin(l, v3, rr), c4, gh[3], fn_iter);

        if (owner) wacc += wts[0] * fn_iter;

        c1 = add4(c1, f0);
        c2 = add4(c2, f1);
        c3 = add4(c3, f2);
        c4 = add4(c4, f3);
        float* hdst = hb[1];
        *(float4*)&hdst[(2 * ty + 0) * SSTR + col] = c1;
        *(float4*)&hdst[(2 * ty + 1) * SSTR + col] = c4;
        __syncthreads();
    }

    // ================= k = 2..5 (no edge handling) =========================
    #pragma unroll
    for (int k = 2; k <= NITER; ++k) {
        const float* hsrc = hb[(k - 1) & 1];
        const float4 htop = *(const float4*)&hsrc[slot_top * SSTR + col];
        const float4 hbot = *(const float4*)&hsrc[slot_bot * SSTR + col];

        const float4 s12 = add4(c1, c2);
        const float4 s34 = add4(c3, c4);
        const float4 v0 = add4(htop, s12);
        const float4 v1 = add4(s12, c3);
        const float4 v2 = add4(c2, s34);
        const float4 v3 = add4(s34, hbot);

        float fn_iter = 0.0f;
        const float4 f0 = pixrow(
            hfin(__shfl_up_sync(0xffffffffu, v0.w, 1), v0,
                 __shfl_down_sync(0xffffffffu, v0.x, 1)), c1, gh[0], fn_iter);
        const float4 f1 = pixrow(
            hfin(__shfl_up_sync(0xffffffffu, v1.w, 1), v1,
                 __shfl_down_sync(0xffffffffu, v1.x, 1)), c2, gh[1], fn_iter);
        const float4 f2 = pixrow(
            hfin(__shfl_up_sync(0xffffffffu, v2.w, 1), v2,
                 __shfl_down_sync(0xffffffffu, v2.x, 1)), c3, gh[2], fn_iter);
        const float4 f3 = pixrow(
            hfin(__shfl_up_sync(0xffffffffu, v3.w, 1), v3,
                 __shfl_down_sync(0xffffffffu, v3.x, 1)), c4, gh[3], fn_iter);

        if (owner) wacc += wts[k - 1] * fn_iter;

        if (k < NITER) {
            c1 = add4(c1, f0);
            c2 = add4(c2, f1);
            c3 = add4(c3, f2);
            c4 = add4(c4, f3);
            float* hdst = hb[k & 1];
            *(float4*)&hdst[(2 * ty + 0) * SSTR + col] = c1;
            *(float4*)&hdst[(2 * ty + 1) * SSTR + col] = c4;
            __syncthreads();
        }
    }

    // ---- block reduction, one atomic each per block; last block finalizes
    #pragma unroll
    for (int o = 16; o > 0; o >>= 1) {
        wacc     += __shfl_down_sync(0xffffffffu, wacc, o);
        gt_local += __shfl_down_sync(0xffffffffu, gt_local, o);
    }
    const int lane = tid & 31;
    const int wid  = tid >> 5;
    if (lane == 0) { red_w[wid] = wacc; red_g[wid] = gt_local; }
    __syncthreads();
    if (tid == 0) {
        float v = 0.0f, g = 0.0f;
        #pragma unroll
        for (int i = 0; i < 8; ++i) { v += red_w[i]; g += red_g[i]; }
        atomicAdd(&g_sums[1], v);
        atomicAdd(&g_sums[0], g);
        __threadfence();
        const unsigned int done = atomicAdd(&g_count, 1u);
        if (done == NBLK - 1) {
            const float s1 = atomicAdd(&g_sums[1], 0.0f);
            const float s0 = atomicAdd(&g_sums[0], 0.0f);
            out[0] = s1 / s0;
            g_sums[0] = 0.0f;
            g_sums[1] = 0.0f;
            g_count   = 0u;
        }
    }
}

extern "C" void kernel_launch(void* const* d_in, const int* in_sizes, int n_in,
                              void* d_out, int out_size) {
    (void)in_sizes; (void)n_in; (void)out_size;
    const float* pred = (const float*)d_in[0];
    const float* gt   = (const float*)d_in[1];
    float* out        = (float*)d_out;

    dim3 block(16, 16);
    dim3 grid(NTILES, NTILES);
    fused_kernel<<<grid, block>>>(pred, gt, out);
}